// round 3
// baseline (speedup 1.0000x reference)
#include <cuda_runtime.h>
#include <math.h>

#define NLEV 16
#define MAX_SIZE (1u << 19)
#define P1 2654435761u
#define P2 805459861u

// Levels resident in shared memory: sizes 4096, 8192, 16384 float2 entries.
#define SM_L0_ENT 4096
#define SM_L1_ENT 8192
#define SM_L2_ENT 16384
#define SM_TOTAL_ENT (SM_L0_ENT + SM_L1_ENT + SM_L2_ENT)   // 28672 float2
#define SMEM_BYTES (SM_TOTAL_ENT * 8)                       // 229376 B

struct LP {
    float    res[NLEV];
    unsigned mask[NLEV];
};

__global__ void __launch_bounds__(1024, 1)
hashgrid_kernel(const float* __restrict__ x,
                const float* __restrict__ tables,
                float* __restrict__ out,
                LP lp, int n)
{
    extern __shared__ float2 stab[];   // [L0 | L1 | L2]

    const int tid = threadIdx.x;

    // Cooperative stage of levels 0..2 into smem (float4 copies).
    {
        const float4* __restrict__ src = reinterpret_cast<const float4*>(tables);
        float4* dst = reinterpret_cast<float4*>(stab);
        // per level: MAX_SIZE float2 = (1<<18) float4 stride in src
        const int S = 1 << 18;
#pragma unroll 2
        for (int i = tid; i < SM_L0_ENT / 2; i += 1024) dst[i] = src[i];
#pragma unroll 2
        for (int i = tid; i < SM_L1_ENT / 2; i += 1024) dst[SM_L0_ENT / 2 + i] = src[S + i];
#pragma unroll 4
        for (int i = tid; i < SM_L2_ENT / 2; i += 1024)
            dst[(SM_L0_ENT + SM_L1_ENT) / 2 + i] = src[2 * S + i];
    }
    __syncthreads();

    const int lane   = tid & 31;
    const int c      = lane & 7;           // corner id within 8-lane group
    const unsigned bx = c & 1;
    const unsigned by = (c >> 1) & 1;
    const unsigned bz = (c >> 2) & 1;

    const int warpsPerGrid = gridDim.x * (blockDim.x >> 5);
    const int w0 = blockIdx.x * (blockDim.x >> 5) + (tid >> 5);

    const int smoff[3] = {0, SM_L0_ENT, SM_L0_ENT + SM_L1_ENT};

    for (int pt = w0 * 4 + (lane >> 3); pt < n; pt += warpsPerGrid * 4) {

        const float px = x[3 * pt + 0];
        const float py = x[3 * pt + 1];
        const float pz = x[3 * pt + 2];

        float2 r[2];

#pragma unroll
        for (int l = 0; l < NLEV; ++l) {
            const float    res  = lp.res[l];
            const unsigned mask = lp.mask[l];

            const float xs = px * res, ys = py * res, zs = pz * res;
            const float fx = floorf(xs), fy = floorf(ys), fz = floorf(zs);

            const unsigned ix = (unsigned)fx + bx;
            const unsigned iy = (unsigned)fy + by;
            const unsigned iz = (unsigned)fz + bz;

            const float xf = xs - fx, yf = ys - fy, zf = zs - fz;
            const float wx = bx ? xf : 1.0f - xf;
            const float wy = by ? yf : 1.0f - yf;
            const float wz = bz ? zf : 1.0f - zf;
            const float w  = wx * wy * wz;

            const unsigned h  = ix ^ (iy * P1) ^ (iz * P2);
            const unsigned id = h & mask;

            float2 f;
            if (l < 3) {
                f = stab[smoff[l] + id];                     // LDS path
            } else {
                const float2* __restrict__ tbl =
                    reinterpret_cast<const float2*>(tables) + (size_t)l * MAX_SIZE;
                f = __ldg(&tbl[id]);                          // L2-gather path
            }

            float vx = w * f.x;
            float vy = w * f.y;

            // sum over the 8 corner lanes
#pragma unroll
            for (int m = 1; m < 8; m <<= 1) {
                vx += __shfl_xor_sync(0xffffffffu, vx, m);
                vy += __shfl_xor_sync(0xffffffffu, vy, m);
            }

            if ((l & 7) == c) r[l >> 3] = make_float2(vx, vy);
        }

        float2* o = reinterpret_cast<float2*>(out + (size_t)pt * 32);
        o[c]     = r[0];
        o[c + 8] = r[1];
    }
}

extern "C" void kernel_launch(void* const* d_in, const int* in_sizes, int n_in,
                              void* d_out, int out_size)
{
    const float* x      = (const float*)d_in[0];
    const float* tables = (const float*)d_in[1];
    float*       out    = (float*)d_out;
    const int    n      = in_sizes[0] / 3;

    // Replicate the reference's level-resolution math EXACTLY in double precision.
    LP lp;
    const double b = exp((log(512.0) - log(16.0)) / 15.0);
    for (int l = 0; l < NLEV; ++l) {
        const double r   = floor(16.0 * pow(b, (double)l));
        const long   res = (long)r;
        long sz = res * res * res;
        if (sz > (1L << 19)) sz = (1L << 19);
        long p = 1;
        while (p < sz) p <<= 1;
        lp.res[l]  = (float)r;
        lp.mask[l] = (unsigned)(p - 1);
    }

    static int configured = 0;
    if (!configured) {
        cudaFuncSetAttribute(hashgrid_kernel,
                             cudaFuncAttributeMaxDynamicSharedMemorySize, SMEM_BYTES);
        configured = 1;
    }

    int dev = 0, sms = 148;
    cudaGetDevice(&dev);
    cudaDeviceGetAttribute(&sms, cudaDevAttrMultiProcessorCount, dev);

    hashgrid_kernel<<<sms, 1024, SMEM_BYTES>>>(x, tables, out, lp, n);
}

// round 5
// speedup vs baseline: 2.0562x; 2.0562x over previous
#include <cuda_runtime.h>
#include <math.h>

#define NLEV 16
#define MAX_SIZE (1u << 19)
#define P1 2654435761u
#define P2 805459861u

#define NPTS_MAX 2097152
#define NBINS (1u << 21)
#define SCAN_BLK 2048
#define NSCANBLKS (NBINS / SCAN_BLK)   // 1024

struct LP {
    float    res[NLEV];
    unsigned mask[NLEV];
};

// Static scratch (allocation-free rule: __device__ globals)
__device__ unsigned d_hist[NBINS];
__device__ unsigned d_scan[NBINS];
__device__ unsigned d_bsums[NSCANBLKS];
__device__ float4   d_sorted[NPTS_MAX];

// ---------------- Morton key (7 bits/dim, res 128 -> 21-bit key) ----------------
__device__ __forceinline__ unsigned expand_bits(unsigned v)
{
    v = (v | (v << 16)) & 0x030000FFu;
    v = (v | (v << 8))  & 0x0300F00Fu;
    v = (v | (v << 4))  & 0x030C30C3u;
    v = (v | (v << 2))  & 0x09249249u;
    return v;
}
__device__ __forceinline__ unsigned morton_key(float px, float py, float pz)
{
    unsigned ix = min(127u, (unsigned)(px * 128.0f));
    unsigned iy = min(127u, (unsigned)(py * 128.0f));
    unsigned iz = min(127u, (unsigned)(pz * 128.0f));
    return expand_bits(ix) | (expand_bits(iy) << 1) | (expand_bits(iz) << 2);
}

// ---------------- Sort pipeline ----------------
__global__ void k_hist(const float* __restrict__ x, int n)
{
    int i = blockIdx.x * blockDim.x + threadIdx.x;
    if (i >= n) return;
    unsigned k = morton_key(x[3 * i], x[3 * i + 1], x[3 * i + 2]);
    atomicAdd(&d_hist[k], 1u);
}

__global__ void __launch_bounds__(1024) k_scan1()
{
    __shared__ unsigned s[SCAN_BLK];
    const int t = threadIdx.x;
    const unsigned base = blockIdx.x * SCAN_BLK;
    s[t] = d_hist[base + t];
    s[t + 1024] = d_hist[base + t + 1024];
    int offset = 1;
    for (int d = SCAN_BLK >> 1; d > 0; d >>= 1) {
        __syncthreads();
        if (t < d) {
            int ai = offset * (2 * t + 1) - 1;
            int bi = offset * (2 * t + 2) - 1;
            s[bi] += s[ai];
        }
        offset <<= 1;
    }
    if (t == 0) { d_bsums[blockIdx.x] = s[SCAN_BLK - 1]; s[SCAN_BLK - 1] = 0; }
    for (int d = 1; d < SCAN_BLK; d <<= 1) {
        offset >>= 1;
        __syncthreads();
        if (t < d) {
            int ai = offset * (2 * t + 1) - 1;
            int bi = offset * (2 * t + 2) - 1;
            unsigned tm = s[ai]; s[ai] = s[bi]; s[bi] += tm;
        }
    }
    __syncthreads();
    d_scan[base + t] = s[t];
    d_scan[base + t + 1024] = s[t + 1024];
}

__global__ void __launch_bounds__(512) k_scan2()
{
    __shared__ unsigned s[NSCANBLKS];
    const int t = threadIdx.x;    // 512 threads, 1024 elements
    s[t] = d_bsums[t];
    s[t + 512] = d_bsums[t + 512];
    int offset = 1;
    for (int d = NSCANBLKS >> 1; d > 0; d >>= 1) {
        __syncthreads();
        if (t < d) {
            int ai = offset * (2 * t + 1) - 1;
            int bi = offset * (2 * t + 2) - 1;
            s[bi] += s[ai];
        }
        offset <<= 1;
    }
    if (t == 0) s[NSCANBLKS - 1] = 0;
    for (int d = 1; d < NSCANBLKS; d <<= 1) {
        offset >>= 1;
        __syncthreads();
        if (t < d) {
            int ai = offset * (2 * t + 1) - 1;
            int bi = offset * (2 * t + 2) - 1;
            unsigned tm = s[ai]; s[ai] = s[bi]; s[bi] += tm;
        }
    }
    __syncthreads();
    d_bsums[t] = s[t];
    d_bsums[t + 512] = s[t + 512];
}

__global__ void k_addoff()
{
    unsigned i = blockIdx.x * blockDim.x + threadIdx.x;
    if (i < NBINS) d_scan[i] += d_bsums[i >> 11];   // 2048 = 1<<11 per scan block
}

__global__ void k_scatter(const float* __restrict__ x, int n)
{
    int i = blockIdx.x * blockDim.x + threadIdx.x;
    if (i >= n) return;
    const float px = x[3 * i], py = x[3 * i + 1], pz = x[3 * i + 2];
    unsigned k = morton_key(px, py, pz);
    unsigned p = atomicAdd(&d_scan[k], 1u);
    d_sorted[p] = make_float4(px, py, pz, __uint_as_float((unsigned)i));
}

// ---------------- Main encode: 8 lanes/corner, 4 points/warp, sorted order ----------------
__global__ void __launch_bounds__(256)
hashgrid_kernel(const float* __restrict__ tables,
                float* __restrict__ out,
                LP lp, int n)
{
    const int lane   = threadIdx.x & 31;
    const int warpid = (blockIdx.x * (blockDim.x >> 5)) + (threadIdx.x >> 5);
    const int pt     = warpid * 4 + (lane >> 3);
    if (pt >= n) return;

    const int c  = lane & 7;
    const unsigned bx = c & 1;
    const unsigned by = (c >> 1) & 1;
    const unsigned bz = (c >> 2) & 1;

    const float4 s4 = d_sorted[pt];
    const float px = s4.x, py = s4.y, pz = s4.z;
    const unsigned oidx = __float_as_uint(s4.w);

    // Lane c keeps levels 2c and 2c+1 -> one contiguous float4 store.
    float4 r;

#pragma unroll
    for (int l = 0; l < NLEV; ++l) {
        const float    res  = lp.res[l];
        const unsigned mask = lp.mask[l];
        const float2* __restrict__ tbl =
            reinterpret_cast<const float2*>(tables) + (size_t)l * MAX_SIZE;

        const float xs = px * res, ys = py * res, zs = pz * res;
        const float fx = floorf(xs), fy = floorf(ys), fz = floorf(zs);

        const unsigned ix = (unsigned)fx + bx;
        const unsigned iy = (unsigned)fy + by;
        const unsigned iz = (unsigned)fz + bz;

        const float xf = xs - fx, yf = ys - fy, zf = zs - fz;
        const float wx = bx ? xf : 1.0f - xf;
        const float wy = by ? yf : 1.0f - yf;
        const float wz = bz ? zf : 1.0f - zf;
        const float w  = wx * wy * wz;

        const unsigned h = ix ^ (iy * P1) ^ (iz * P2);
        const float2   f = __ldg(&tbl[h & mask]);

        float vx = w * f.x;
        float vy = w * f.y;

#pragma unroll
        for (int m = 1; m < 8; m <<= 1) {
            vx += __shfl_xor_sync(0xffffffffu, vx, m);
            vy += __shfl_xor_sync(0xffffffffu, vy, m);
        }

        if ((l >> 1) == c) {
            if (l & 1) { r.z = vx; r.w = vy; }
            else       { r.x = vx; r.y = vy; }
        }
    }

    float4* o = reinterpret_cast<float4*>(out + (size_t)oidx * 32);
    o[c] = r;
}

extern "C" void kernel_launch(void* const* d_in, const int* in_sizes, int n_in,
                              void* d_out, int out_size)
{
    const float* x      = (const float*)d_in[0];
    const float* tables = (const float*)d_in[1];
    float*       out    = (float*)d_out;
    const int    n      = in_sizes[0] / 3;

    // Replicate the reference's level-resolution math EXACTLY in double precision.
    LP lp;
    const double b = exp((log(512.0) - log(16.0)) / 15.0);
    for (int l = 0; l < NLEV; ++l) {
        const double r   = floor(16.0 * pow(b, (double)l));
        const long   res = (long)r;
        long sz = res * res * res;
        if (sz > (1L << 19)) sz = (1L << 19);
        long p = 1;
        while (p < sz) p <<= 1;
        lp.res[l]  = (float)r;
        lp.mask[l] = (unsigned)(p - 1);
    }

    static void* hist_ptr = nullptr;
    if (!hist_ptr) cudaGetSymbolAddress(&hist_ptr, d_hist);

    // 1) zero histogram
    cudaMemsetAsync(hist_ptr, 0, NBINS * sizeof(unsigned), 0);

    // 2) histogram of morton keys
    k_hist<<<(n + 255) / 256, 256>>>(x, n);

    // 3) exclusive scan (block-level + block sums + fixup)
    k_scan1<<<NSCANBLKS, 1024>>>();
    k_scan2<<<1, 512>>>();
    k_addoff<<<NBINS / 1024, 1024>>>();

    // 4) scatter points into morton order (orig idx in .w)
    k_scatter<<<(n + 255) / 256, 256>>>(x, n);

    // 5) encode
    const int threads = 256;                 // 8 warps -> 32 points per block
    const int pts_per_block = (threads / 32) * 4;
    const int blocks = (n + pts_per_block - 1) / pts_per_block;
    hashgrid_kernel<<<blocks, threads>>>(tables, out, lp, n);
}

// round 6
// speedup vs baseline: 2.1566x; 1.0488x over previous
#include <cuda_runtime.h>
#include <math.h>

#define NLEV 16
#define MAX_SIZE (1u << 19)
#define P1 2654435761u
#define P2 805459861u

#define NPTS_MAX 2097152
#define KEY_BITS_DIM 6                  // res-64 Morton key
#define NBINS (1u << (3 * KEY_BITS_DIM)) // 262144 bins, ~8 pts/bin
#define SCAN_BLK 2048
#define NSCANBLKS (NBINS / SCAN_BLK)    // 128

struct LP {
    float    res[NLEV];
    unsigned mask[NLEV];
};

// Static scratch (allocation-free rule: __device__ globals)
__device__ unsigned d_hist[NBINS];      // becomes intra-block exclusive scan
__device__ unsigned d_bsums[NSCANBLKS]; // exclusive scan of block sums
__device__ float4   d_sorted[NPTS_MAX];

// ---------------- Morton key (6 bits/dim -> 18-bit key) ----------------
__device__ __forceinline__ unsigned expand_bits(unsigned v)
{
    v = (v | (v << 16)) & 0x030000FFu;
    v = (v | (v << 8))  & 0x0300F00Fu;
    v = (v | (v << 4))  & 0x030C30C3u;
    v = (v | (v << 2))  & 0x09249249u;
    return v;
}
__device__ __forceinline__ unsigned morton_key(float px, float py, float pz)
{
    unsigned ix = min(63u, (unsigned)(px * 64.0f));
    unsigned iy = min(63u, (unsigned)(py * 64.0f));
    unsigned iz = min(63u, (unsigned)(pz * 64.0f));
    return expand_bits(ix) | (expand_bits(iy) << 1) | (expand_bits(iz) << 2);
}

// ---------------- Sort pipeline ----------------
__global__ void k_hist(const float* __restrict__ x, int n)
{
    int i = blockIdx.x * blockDim.x + threadIdx.x;
    if (i >= n) return;
    unsigned k = morton_key(x[3 * i], x[3 * i + 1], x[3 * i + 2]);
    atomicAdd(&d_hist[k], 1u);
}

// In-place Blelloch scan of d_hist per 2048-bin block; block totals to d_bsums.
__global__ void __launch_bounds__(1024) k_scan1()
{
    __shared__ unsigned s[SCAN_BLK];
    const int t = threadIdx.x;
    const unsigned base = blockIdx.x * SCAN_BLK;
    s[t] = d_hist[base + t];
    s[t + 1024] = d_hist[base + t + 1024];
    int offset = 1;
    for (int d = SCAN_BLK >> 1; d > 0; d >>= 1) {
        __syncthreads();
        if (t < d) {
            int ai = offset * (2 * t + 1) - 1;
            int bi = offset * (2 * t + 2) - 1;
            s[bi] += s[ai];
        }
        offset <<= 1;
    }
    if (t == 0) { d_bsums[blockIdx.x] = s[SCAN_BLK - 1]; s[SCAN_BLK - 1] = 0; }
    for (int d = 1; d < SCAN_BLK; d <<= 1) {
        offset >>= 1;
        __syncthreads();
        if (t < d) {
            int ai = offset * (2 * t + 1) - 1;
            int bi = offset * (2 * t + 2) - 1;
            unsigned tm = s[ai]; s[ai] = s[bi]; s[bi] += tm;
        }
    }
    __syncthreads();
    d_hist[base + t] = s[t];
    d_hist[base + t + 1024] = s[t + 1024];
}

// Exclusive scan of the 128 block sums (single warp-friendly block).
__global__ void __launch_bounds__(128) k_scan2()
{
    __shared__ unsigned s[NSCANBLKS];
    const int t = threadIdx.x;
    s[t] = d_bsums[t];
    __syncthreads();
    // simple Hillis-Steele inclusive, then shift to exclusive
    unsigned v = s[t];
    for (int d = 1; d < NSCANBLKS; d <<= 1) {
        unsigned add = (t >= d) ? s[t - d] : 0u;
        __syncthreads();
        v += add;
        s[t] = v;
        __syncthreads();
    }
    d_bsums[t] = (t == 0) ? 0u : s[t - 1];
}

// Scatter: global offset = local scan + block-sum prefix (fused, no addoff pass).
__global__ void k_scatter(const float* __restrict__ x, int n)
{
    int i = blockIdx.x * blockDim.x + threadIdx.x;
    if (i >= n) return;
    const float px = x[3 * i], py = x[3 * i + 1], pz = x[3 * i + 2];
    unsigned k = morton_key(px, py, pz);
    unsigned p = atomicAdd(&d_hist[k], 1u) + d_bsums[k >> 11];
    d_sorted[p] = make_float4(px, py, pz, __uint_as_float((unsigned)i));
}

// ---------------- Main encode: 8 lanes/corner, 4 points/warp, sorted order ----------------
__global__ void __launch_bounds__(256)
hashgrid_kernel(const float* __restrict__ tables,
                float* __restrict__ out,
                LP lp, int n)
{
    const int lane   = threadIdx.x & 31;
    const int warpid = (blockIdx.x * (blockDim.x >> 5)) + (threadIdx.x >> 5);
    const int pt     = warpid * 4 + (lane >> 3);
    if (pt >= n) return;

    const int c  = lane & 7;
    const unsigned bx = c & 1;
    const unsigned by = (c >> 1) & 1;
    const unsigned bz = (c >> 2) & 1;

    const float4 s4 = d_sorted[pt];
    const float px = s4.x, py = s4.y, pz = s4.z;
    const unsigned oidx = __float_as_uint(s4.w);

    // Lane c keeps levels 2c and 2c+1 -> one contiguous float4 store.
    float4 r;

#pragma unroll
    for (int l = 0; l < NLEV; ++l) {
        const float    res  = lp.res[l];
        const unsigned mask = lp.mask[l];
        const float2* __restrict__ tbl =
            reinterpret_cast<const float2*>(tables) + (size_t)l * MAX_SIZE;

        const float xs = px * res, ys = py * res, zs = pz * res;
        const float fx = floorf(xs), fy = floorf(ys), fz = floorf(zs);

        const unsigned ix = (unsigned)fx + bx;
        const unsigned iy = (unsigned)fy + by;
        const unsigned iz = (unsigned)fz + bz;

        const float xf = xs - fx, yf = ys - fy, zf = zs - fz;
        const float wx = bx ? xf : 1.0f - xf;
        const float wy = by ? yf : 1.0f - yf;
        const float wz = bz ? zf : 1.0f - zf;
        const float w  = wx * wy * wz;

        const unsigned h = ix ^ (iy * P1) ^ (iz * P2);
        const float2   f = __ldg(&tbl[h & mask]);

        float vx = w * f.x;
        float vy = w * f.y;

#pragma unroll
        for (int m = 1; m < 8; m <<= 1) {
            vx += __shfl_xor_sync(0xffffffffu, vx, m);
            vy += __shfl_xor_sync(0xffffffffu, vy, m);
        }

        if ((l >> 1) == c) {
            if (l & 1) { r.z = vx; r.w = vy; }
            else       { r.x = vx; r.y = vy; }
        }
    }

    float4* o = reinterpret_cast<float4*>(out + (size_t)oidx * 32);
    o[c] = r;
}

extern "C" void kernel_launch(void* const* d_in, const int* in_sizes, int n_in,
                              void* d_out, int out_size)
{
    const float* x      = (const float*)d_in[0];
    const float* tables = (const float*)d_in[1];
    float*       out    = (float*)d_out;
    const int    n      = in_sizes[0] / 3;

    // Replicate the reference's level-resolution math EXACTLY in double precision.
    LP lp;
    const double b = exp((log(512.0) - log(16.0)) / 15.0);
    for (int l = 0; l < NLEV; ++l) {
        const double r   = floor(16.0 * pow(b, (double)l));
        const long   res = (long)r;
        long sz = res * res * res;
        if (sz > (1L << 19)) sz = (1L << 19);
        long p = 1;
        while (p < sz) p <<= 1;
        lp.res[l]  = (float)r;
        lp.mask[l] = (unsigned)(p - 1);
    }

    static void* hist_ptr = nullptr;
    if (!hist_ptr) cudaGetSymbolAddress(&hist_ptr, d_hist);

    // 1) zero histogram (1 MB)
    cudaMemsetAsync(hist_ptr, 0, NBINS * sizeof(unsigned), 0);

    // 2) histogram of 18-bit morton keys
    k_hist<<<(n + 255) / 256, 256>>>(x, n);

    // 3) two-level exclusive scan (no fixup pass; bsums added at scatter)
    k_scan1<<<NSCANBLKS, 1024>>>();
    k_scan2<<<1, 128>>>();

    // 4) scatter points into morton order (orig idx in .w)
    k_scatter<<<(n + 255) / 256, 256>>>(x, n);

    // 5) encode
    const int threads = 256;                 // 8 warps -> 32 points per block
    const int pts_per_block = (threads / 32) * 4;
    const int blocks = (n + pts_per_block - 1) / pts_per_block;
    hashgrid_kernel<<<blocks, threads>>>(tables, out, lp, n);
}